// round 1
// baseline (speedup 1.0000x reference)
#include <cuda_runtime.h>
#include <math.h>

#define B_DIM   8
#define HW_DIM  3136
#define C_DIM   256
#define NROWS   (B_DIM * HW_DIM)        // 25088
#define PITCH   68                      // smem row pitch (floats), 16B-aligned rows
#define MT      64                      // i/j tile size

// Scratch (device globals — no allocations allowed in kernel_launch)
__device__ float g_xn[(size_t)NROWS * C_DIM];   // L2-normalized x
__device__ float g_t [(size_t)NROWS * C_DIM];   // transform branch x@W

// ---------------------------------------------------------------------------
// Kernel A: row-wise L2 normalize.  One warp per row (256 floats = 2 float4/lane)
// ---------------------------------------------------------------------------
__global__ void norm_kernel(const float* __restrict__ x) {
    int row  = blockIdx.x * 8 + threadIdx.y;
    int lane = threadIdx.x;
    const float4* xr = reinterpret_cast<const float4*>(x) + (size_t)row * (C_DIM / 4);
    float4 v0 = xr[lane];
    float4 v1 = xr[lane + 32];
    float s = v0.x * v0.x + v0.y * v0.y + v0.z * v0.z + v0.w * v0.w
            + v1.x * v1.x + v1.y * v1.y + v1.z * v1.z + v1.w * v1.w;
#pragma unroll
    for (int off = 16; off > 0; off >>= 1)
        s += __shfl_xor_sync(0xffffffffu, s, off);
    float inv = rsqrtf(fmaxf(s, 1e-12f));   // matches tf.nn.l2_normalize eps
    v0.x *= inv; v0.y *= inv; v0.z *= inv; v0.w *= inv;
    v1.x *= inv; v1.y *= inv; v1.z *= inv; v1.w *= inv;
    float4* o = reinterpret_cast<float4*>(g_xn) + (size_t)row * (C_DIM / 4);
    o[lane]      = v0;
    o[lane + 32] = v1;
}

// ---------------------------------------------------------------------------
// Kernel B: t = x @ W   (25088 x 256 x 256).  64x64 tile / CTA, 4x4 micro-tile.
// ---------------------------------------------------------------------------
__global__ __launch_bounds__(256)
void transform_kernel(const float* __restrict__ x, const float* __restrict__ W) {
    __shared__ float sXT[64 * PITCH];   // [k][i]  (transposed X tile)
    __shared__ float sWS[64 * PITCH];   // [k][c]

    int row0 = blockIdx.x * 64;
    int c0   = blockIdx.y * 64;
    int tid  = threadIdx.x;
    int tx   = tid & 15, ty = tid >> 4;

    float acc[4][4] = {};

    for (int k0 = 0; k0 < C_DIM; k0 += 64) {
        __syncthreads();
#pragma unroll
        for (int q = 0; q < 16; q++) {
            int idx = tid + q * 256;            // 0..4095
            int a   = idx >> 6;                 // 0..63
            int bcol = idx & 63;                // 0..63
            // X tile: a = row i, bcol = k  -> store transposed [k][i]
            sXT[bcol * PITCH + a] = x[(size_t)(row0 + a) * C_DIM + k0 + bcol];
            // W tile: a = k, bcol = c      -> store natural [k][c]
            sWS[a * PITCH + bcol] = W[(size_t)(k0 + a) * C_DIM + c0 + bcol];
        }
        __syncthreads();
#pragma unroll 8
        for (int kk = 0; kk < 64; kk++) {
            float4 av = *reinterpret_cast<const float4*>(&sXT[kk * PITCH + 4 * ty]);
            float4 bv = *reinterpret_cast<const float4*>(&sWS[kk * PITCH + 4 * tx]);
            float aq[4] = {av.x, av.y, av.z, av.w};
            float br[4] = {bv.x, bv.y, bv.z, bv.w};
#pragma unroll
            for (int q = 0; q < 4; q++)
#pragma unroll
                for (int r = 0; r < 4; r++)
                    acc[q][r] += aq[q] * br[r];
        }
    }
#pragma unroll
    for (int q = 0; q < 4; q++) {
        float4 v = make_float4(acc[q][0], acc[q][1], acc[q][2], acc[q][3]);
        *reinterpret_cast<float4*>(
            &g_t[(size_t)(row0 + 4 * ty + q) * C_DIM + c0 + 4 * tx]) = v;
    }
}

// ---------------------------------------------------------------------------
// Kernel C: fused attention-like pass.
//   Per CTA: 64 i-rows of one batch.  Xi tile resident in smem (k-major).
//   Loop over j-tiles:  S = Xi @ Xj^T  -> relu^2 -> smem  -> Y += S @ Tj
//   sT aliases sXjT (phase separation enforced by barriers).
// ---------------------------------------------------------------------------
__global__ __launch_bounds__(256)
void ppm_fused(float* __restrict__ y) {
    extern __shared__ float smem[];
    float* sXiT = smem;                          // [256][PITCH]   (k-major)
    float* sXjT = smem + C_DIM * PITCH;          // [256][PITCH]   (k-major)
    float* sS   = smem + 2 * C_DIM * PITCH;      // [64][PITCH]
    float* sT   = sXjT;                          // alias: [64][256] row-major

    int b  = blockIdx.y;
    int i0 = blockIdx.x * MT;
    const float* Xb = g_xn + (size_t)b * HW_DIM * C_DIM;
    const float* Tb = g_t  + (size_t)b * HW_DIM * C_DIM;

    int tid = threadIdx.x;
    int tx  = tid & 15, ty = tid >> 4;

    // Load Xi transposed: thread owns channel c = tid, iterates rows.
    {
        const float* src = Xb + (size_t)i0 * C_DIM + tid;
#pragma unroll 8
        for (int i = 0; i < MT; i++)
            sXiT[tid * PITCH + i] = src[(size_t)i * C_DIM];
    }

    float4 yacc[4][4];
#pragma unroll
    for (int q = 0; q < 4; q++)
#pragma unroll
        for (int s = 0; s < 4; s++)
            yacc[q][s] = make_float4(0.f, 0.f, 0.f, 0.f);

    for (int j0 = 0; j0 < HW_DIM; j0 += MT) {
        __syncthreads();   // prev iter done reading sT before sXjT overwrite

        // Load Xj transposed
        {
            const float* src = Xb + (size_t)j0 * C_DIM + tid;
#pragma unroll 8
            for (int jj = 0; jj < MT; jj++)
                sXjT[tid * PITCH + jj] = src[(size_t)jj * C_DIM];
        }
        __syncthreads();

        // Phase 1: S[64][64] = Xi @ Xj^T   (4x4 per thread, vector smem reads)
        float sreg[4][4] = {};
#pragma unroll 8
        for (int k = 0; k < C_DIM; k++) {
            float4 av = *reinterpret_cast<const float4*>(&sXiT[k * PITCH + 4 * ty]);
            float4 bv = *reinterpret_cast<const float4*>(&sXjT[k * PITCH + 4 * tx]);
            float aq[4] = {av.x, av.y, av.z, av.w};
            float br[4] = {bv.x, bv.y, bv.z, bv.w};
#pragma unroll
            for (int q = 0; q < 4; q++)
#pragma unroll
                for (int r = 0; r < 4; r++)
                    sreg[q][r] += aq[q] * br[r];
        }
        // relu(s)^2 -> sS
#pragma unroll
        for (int q = 0; q < 4; q++)
#pragma unroll
            for (int r = 0; r < 4; r++) {
                float v = fmaxf(sreg[q][r], 0.f);
                sS[(4 * ty + q) * PITCH + 4 * tx + r] = v * v;
            }
        __syncthreads();   // all phase-1 reads of sXjT done; sS visible

        // Load T tile into the aliased buffer
        {
            const float* src = Tb + (size_t)j0 * C_DIM + tid;
#pragma unroll 8
            for (int jj = 0; jj < MT; jj++)
                sT[jj * C_DIM + tid] = src[(size_t)jj * C_DIM];
        }
        __syncthreads();

        // Phase 2: Y[64][256] += S @ T
#pragma unroll 2
        for (int jj = 0; jj < MT; jj++) {
            float a0 = sS[(4 * ty + 0) * PITCH + jj];
            float a1 = sS[(4 * ty + 1) * PITCH + jj];
            float a2 = sS[(4 * ty + 2) * PITCH + jj];
            float a3 = sS[(4 * ty + 3) * PITCH + jj];
#pragma unroll
            for (int s = 0; s < 4; s++) {
                float4 bv = *reinterpret_cast<const float4*>(
                    &sT[jj * C_DIM + 4 * tx + 64 * s]);
                yacc[0][s].x += a0 * bv.x; yacc[0][s].y += a0 * bv.y;
                yacc[0][s].z += a0 * bv.z; yacc[0][s].w += a0 * bv.w;
                yacc[1][s].x += a1 * bv.x; yacc[1][s].y += a1 * bv.y;
                yacc[1][s].z += a1 * bv.z; yacc[1][s].w += a1 * bv.w;
                yacc[2][s].x += a2 * bv.x; yacc[2][s].y += a2 * bv.y;
                yacc[2][s].z += a2 * bv.z; yacc[2][s].w += a2 * bv.w;
                yacc[3][s].x += a3 * bv.x; yacc[3][s].y += a3 * bv.y;
                yacc[3][s].z += a3 * bv.z; yacc[3][s].w += a3 * bv.w;
            }
        }
    }

    // Epilogue: write Y (coalesced float4 stores)
    float* Yb = y + (size_t)b * HW_DIM * C_DIM;
#pragma unroll
    for (int q = 0; q < 4; q++)
#pragma unroll
        for (int s = 0; s < 4; s++)
            *reinterpret_cast<float4*>(
                &Yb[(size_t)(i0 + 4 * ty + q) * C_DIM + 4 * tx + 64 * s]) = yacc[q][s];
}

// ---------------------------------------------------------------------------
extern "C" void kernel_launch(void* const* d_in, const int* in_sizes, int n_in,
                              void* d_out, int out_size) {
    const float* x = (const float*)d_in[0];   // [8,56,56,256] fp32
    const float* W = (const float*)d_in[1];   // [256,256] fp32
    float* y = (float*)d_out;                 // [8,56,56,256] fp32

    (void)in_sizes; (void)n_in; (void)out_size;

    // A: normalize (3136 blocks x (32,8) = 25088 rows)
    norm_kernel<<<HW_DIM, dim3(32, 8)>>>(x);

    // B: t = x @ W
    transform_kernel<<<dim3(NROWS / 64, C_DIM / 64), 256>>>(x, W);

    // C: fused sim/weight/aggregate
    size_t shmem = (size_t)(2 * C_DIM * PITCH + 64 * PITCH) * sizeof(float); // 156672 B
    cudaFuncSetAttribute(ppm_fused, cudaFuncAttributeMaxDynamicSharedMemorySize,
                         (int)shmem);
    ppm_fused<<<dim3(HW_DIM / MT, B_DIM), 256, shmem>>>(y);
}

// round 3
// speedup vs baseline: 2.5536x; 2.5536x over previous
#include <cuda_runtime.h>
#include <math.h>
#include <stdint.h>

#define B_DIM   8
#define HW_DIM  3136
#define C_DIM   256
#define NROWS   (B_DIM * HW_DIM)        // 25088
#define MT      64                      // i/j tile size
#define XPITCH  272                     // [row][k] pitch (floats): conflict-free .128 frags
#define SPITCH  80                      // S pitch: conflict-free .128 frags
#define TPITCH  257                     // T pitch: conflict-free scalar B frags
#define PITCH   68                      // transform kernel smem pitch

// Scratch (device globals — no allocations allowed)
__device__ float g_xn[(size_t)NROWS * C_DIM];   // L2-normalized x
__device__ float g_t [(size_t)NROWS * C_DIM];   // transform branch x@W (fp32 exact)

// fp32 -> tf32 with round-to-nearest (critical: implicit mma truncation is RZ)
__device__ __forceinline__ uint32_t f2tf(float f) {
    uint32_t u;
    asm("cvt.rna.tf32.f32 %0, %1;" : "=r"(u) : "f"(f));
    return u;
}

__device__ __forceinline__ void mma8(float* d, const uint32_t* a,
                                     uint32_t b0, uint32_t b1) {
    asm volatile(
        "mma.sync.aligned.m16n8k8.row.col.f32.tf32.tf32.f32 "
        "{%0,%1,%2,%3}, {%4,%5,%6,%7}, {%8,%9}, {%0,%1,%2,%3};"
        : "+f"(d[0]), "+f"(d[1]), "+f"(d[2]), "+f"(d[3])
        : "r"(a[0]), "r"(a[1]), "r"(a[2]), "r"(a[3]), "r"(b0), "r"(b1));
}

// ---------------------------------------------------------------------------
// Kernel A: row-wise L2 normalize. One warp per row; MUST cover all NROWS rows.
// ---------------------------------------------------------------------------
__global__ void norm_kernel(const float* __restrict__ x) {
    int row  = blockIdx.x * 8 + threadIdx.y;
    int lane = threadIdx.x;
    const float4* xr = reinterpret_cast<const float4*>(x) + (size_t)row * (C_DIM / 4);
    float4 v0 = xr[lane];
    float4 v1 = xr[lane + 32];
    float s = v0.x * v0.x + v0.y * v0.y + v0.z * v0.z + v0.w * v0.w
            + v1.x * v1.x + v1.y * v1.y + v1.z * v1.z + v1.w * v1.w;
#pragma unroll
    for (int off = 16; off > 0; off >>= 1)
        s += __shfl_xor_sync(0xffffffffu, s, off);
    float inv = rsqrtf(fmaxf(s, 1e-12f));
    v0.x *= inv; v0.y *= inv; v0.z *= inv; v0.w *= inv;
    v1.x *= inv; v1.y *= inv; v1.z *= inv; v1.w *= inv;
    float4* o = reinterpret_cast<float4*>(g_xn) + (size_t)row * (C_DIM / 4);
    o[lane]      = v0;
    o[lane + 32] = v1;
}

// ---------------------------------------------------------------------------
// Kernel B: t = x @ W, SIMT fp32 (kept exact so t carries no tf32 error)
// ---------------------------------------------------------------------------
__global__ __launch_bounds__(256)
void transform_kernel(const float* __restrict__ x, const float* __restrict__ W) {
    __shared__ float sXT[64 * PITCH];   // [k][i]
    __shared__ float sWS[64 * PITCH];   // [k][c]

    int row0 = blockIdx.x * 64;
    int c0   = blockIdx.y * 64;
    int tid  = threadIdx.x;
    int tx   = tid & 15, ty = tid >> 4;

    float acc[4][4] = {};

    for (int k0 = 0; k0 < C_DIM; k0 += 64) {
        __syncthreads();
#pragma unroll
        for (int q = 0; q < 16; q++) {
            int idx = tid + q * 256;
            int a   = idx >> 6;
            int bcol = idx & 63;
            sXT[bcol * PITCH + a] = x[(size_t)(row0 + a) * C_DIM + k0 + bcol];
            sWS[a * PITCH + bcol] = W[(size_t)(k0 + a) * C_DIM + c0 + bcol];
        }
        __syncthreads();
#pragma unroll 8
        for (int kk = 0; kk < 64; kk++) {
            float4 av = *reinterpret_cast<const float4*>(&sXT[kk * PITCH + 4 * ty]);
            float4 bv = *reinterpret_cast<const float4*>(&sWS[kk * PITCH + 4 * tx]);
            float aq[4] = {av.x, av.y, av.z, av.w};
            float br[4] = {bv.x, bv.y, bv.z, bv.w};
#pragma unroll
            for (int q = 0; q < 4; q++)
#pragma unroll
                for (int r = 0; r < 4; r++)
                    acc[q][r] += aq[q] * br[r];
        }
    }
#pragma unroll
    for (int q = 0; q < 4; q++) {
        float4 v = make_float4(acc[q][0], acc[q][1], acc[q][2], acc[q][3]);
        *reinterpret_cast<float4*>(
            &g_t[(size_t)(row0 + 4 * ty + q) * C_DIM + c0 + 4 * tx]) = v;
    }
}

// ---------------------------------------------------------------------------
// Kernel C: fused pass on tensor cores (mma.sync tf32).
//   Per CTA (256 thr = 8 warps): 64 i-rows of one batch.
//   Phase 1: S = Xi @ Xj^T  (warp grid 4x2, warp tile 16x32)
//   Phase 2: Y += relu(S)^2 @ T  (warp grid 4x2, warp tile 16x128)
//   k-slot permutation lets all A/B (phase1) fragments load via LDS.128.
// ---------------------------------------------------------------------------
__global__ __launch_bounds__(256)
void ppm_fused(float* __restrict__ y) {
    extern __shared__ uint32_t sm[];
    uint32_t* sXi = sm;                         // [64][XPITCH] tf32 bits
    uint32_t* sXj = sm + MT * XPITCH;           // [64][XPITCH]
    uint32_t* sS  = sm + 2 * MT * XPITCH;       // [64][SPITCH]
    uint32_t* sT  = sXj;                        // alias: [64][TPITCH]

    int b  = blockIdx.y;
    int i0 = blockIdx.x * MT;
    const float* Xb = g_xn + (size_t)b * HW_DIM * C_DIM;
    const float* Tb = g_t  + (size_t)b * HW_DIM * C_DIM;

    int tid  = threadIdx.x;
    int w    = tid >> 5, lane = tid & 31;
    int gid  = lane >> 2, tig = lane & 3;
    int wr   = w & 3;        // 16-row group (both phases)
    int wc   = w >> 2;       // phase1: 32-col group; phase2: 128-col half
    int r1   = 16 * wr + gid;

    // Load Xi tile (tf32-rounded), row-major [i][k]
#pragma unroll
    for (int it = 0; it < 16; it++) {
        int idx = tid + it * 256;           // 0..4095 over 64 rows x 64 float4
        int r = idx >> 6, c4 = (idx & 63) * 4;
        float4 v = *reinterpret_cast<const float4*>(&Xb[(size_t)(i0 + r) * C_DIM + c4]);
        uint4 t;
        t.x = f2tf(v.x); t.y = f2tf(v.y); t.z = f2tf(v.z); t.w = f2tf(v.w);
        *reinterpret_cast<uint4*>(&sXi[r * XPITCH + c4]) = t;
    }

    float yacc[16][4];
#pragma unroll
    for (int nt = 0; nt < 16; nt++)
#pragma unroll
        for (int q = 0; q < 4; q++) yacc[nt][q] = 0.f;

    for (int j0 = 0; j0 < HW_DIM; j0 += MT) {
        __syncthreads();    // prev phase-2 reads of sT done before overwrite

        // Load Xj tile (tf32-rounded)
#pragma unroll
        for (int it = 0; it < 16; it++) {
            int idx = tid + it * 256;
            int r = idx >> 6, c4 = (idx & 63) * 4;
            float4 v = *reinterpret_cast<const float4*>(&Xb[(size_t)(j0 + r) * C_DIM + c4]);
            uint4 t;
            t.x = f2tf(v.x); t.y = f2tf(v.y); t.z = f2tf(v.z); t.w = f2tf(v.w);
            *reinterpret_cast<uint4*>(&sXj[r * XPITCH + c4]) = t;
        }
        __syncthreads();

        // ---- Phase 1: S(16x32 per warp) = Xi @ Xj^T
        float sacc[4][4] = {};
        int p1n0 = 32 * wc;
#pragma unroll
        for (int kb = 0; kb < C_DIM; kb += 32) {
            uint32_t alo0[4], alo1[4], ahi0[4], ahi1[4];
            *(uint4*)alo0 = *(const uint4*)&sXi[r1 * XPITCH + kb + 4 * tig];
            *(uint4*)alo1 = *(const uint4*)&sXi[(r1 + 8) * XPITCH + kb + 4 * tig];
            *(uint4*)ahi0 = *(const uint4*)&sXi[r1 * XPITCH + kb + 16 + 4 * tig];
            *(uint4*)ahi1 = *(const uint4*)&sXi[(r1 + 8) * XPITCH + kb + 16 + 4 * tig];
            uint32_t blo[4][4], bhi[4][4];
#pragma unroll
            for (int nt = 0; nt < 4; nt++) {
                int n = p1n0 + 8 * nt + gid;
                *(uint4*)blo[nt] = *(const uint4*)&sXj[n * XPITCH + kb + 4 * tig];
                *(uint4*)bhi[nt] = *(const uint4*)&sXj[n * XPITCH + kb + 16 + 4 * tig];
            }
#pragma unroll
            for (int s = 0; s < 4; s++) {
                uint32_t afrag[4] = {alo0[s], alo1[s], ahi0[s], ahi1[s]};
#pragma unroll
                for (int nt = 0; nt < 4; nt++)
                    mma8(sacc[nt], afrag, blo[nt][s], bhi[nt][s]);
            }
        }
        // relu^2 -> sS (tf32-rounded)
#pragma unroll
        for (int nt = 0; nt < 4; nt++) {
            int cc = p1n0 + 8 * nt + 2 * tig;
            float v0 = fmaxf(sacc[nt][0], 0.f), v1 = fmaxf(sacc[nt][1], 0.f);
            float v2 = fmaxf(sacc[nt][2], 0.f), v3 = fmaxf(sacc[nt][3], 0.f);
            sS[r1 * SPITCH + cc]           = f2tf(v0 * v0);
            sS[r1 * SPITCH + cc + 1]       = f2tf(v1 * v1);
            sS[(r1 + 8) * SPITCH + cc]     = f2tf(v2 * v2);
            sS[(r1 + 8) * SPITCH + cc + 1] = f2tf(v3 * v3);
        }
        __syncthreads();    // phase-1 reads of sXj done; sS visible

        // Load T tile into aliased buffer (tf32-rounded), pitch 257
#pragma unroll
        for (int it = 0; it < 16; it++) {
            int idx = tid + it * 256;
            int r = idx >> 6, c4 = (idx & 63) * 4;
            float4 v = *reinterpret_cast<const float4*>(&Tb[(size_t)(j0 + r) * C_DIM + c4]);
            uint32_t* d = &sT[r * TPITCH + c4];
            d[0] = f2tf(v.x); d[1] = f2tf(v.y); d[2] = f2tf(v.z); d[3] = f2tf(v.w);
        }
        __syncthreads();

        // ---- Phase 2: Y(16x128 per warp) += S @ T
        int cb = 128 * wc;
#pragma unroll
        for (int kb = 0; kb < MT; kb += 32) {
            uint32_t alo0[4], alo1[4], ahi0[4], ahi1[4];
            *(uint4*)alo0 = *(const uint4*)&sS[r1 * SPITCH + kb + 4 * tig];
            *(uint4*)alo1 = *(const uint4*)&sS[(r1 + 8) * SPITCH + kb + 4 * tig];
            *(uint4*)ahi0 = *(const uint4*)&sS[r1 * SPITCH + kb + 16 + 4 * tig];
            *(uint4*)ahi1 = *(const uint4*)&sS[(r1 + 8) * SPITCH + kb + 16 + 4 * tig];
#pragma unroll
            for (int s = 0; s < 4; s++) {
                uint32_t afrag[4] = {alo0[s], alo1[s], ahi0[s], ahi1[s]};
                const uint32_t* b0row = &sT[(kb + 4 * tig + s) * TPITCH + cb + gid];
                const uint32_t* b1row = &sT[(kb + 16 + 4 * tig + s) * TPITCH + cb + gid];
#pragma unroll
                for (int nt = 0; nt < 16; nt++)
                    mma8(yacc[nt], afrag, b0row[8 * nt], b1row[8 * nt]);
            }
        }
    }

    // Epilogue: write Y (fp32 exact accumulators)
    float* Yb = y + (size_t)b * HW_DIM * C_DIM;
    int orow = i0 + 16 * wr + gid;
#pragma unroll
    for (int nt = 0; nt < 16; nt++) {
        int col = 128 * wc + 8 * nt + 2 * tig;
        *reinterpret_cast<float2*>(&Yb[(size_t)orow * C_DIM + col]) =
            make_float2(yacc[nt][0], yacc[nt][1]);
        *reinterpret_cast<float2*>(&Yb[(size_t)(orow + 8) * C_DIM + col]) =
            make_float2(yacc[nt][2], yacc[nt][3]);
    }
}

// ---------------------------------------------------------------------------
extern "C" void kernel_launch(void* const* d_in, const int* in_sizes, int n_in,
                              void* d_out, int out_size) {
    const float* x = (const float*)d_in[0];   // [8,56,56,256] fp32
    const float* W = (const float*)d_in[1];   // [256,256] fp32
    float* y = (float*)d_out;                 // [8,56,56,256] fp32

    (void)in_sizes; (void)n_in; (void)out_size;

    // A: normalize ALL NROWS = 25088 rows (8 rows per block -> 3136 blocks)
    norm_kernel<<<NROWS / 8, dim3(32, 8)>>>(x);

    transform_kernel<<<dim3(NROWS / 64, C_DIM / 64), 256>>>(x, W);

    size_t shmem = (size_t)(2 * MT * XPITCH + MT * SPITCH) * sizeof(uint32_t); // 159744
    cudaFuncSetAttribute(ppm_fused, cudaFuncAttributeMaxDynamicSharedMemorySize,
                         (int)shmem);
    ppm_fused<<<dim3(HW_DIM / MT, B_DIM), 256, shmem>>>(y);
}